// round 9
// baseline (speedup 1.0000x reference)
#include <cuda_runtime.h>
#define DI __device__ __forceinline__

namespace {
constexpr int B = 32, N = 16384, S = 7, D = 64;
constexpr int BN = B * N, BSl = B * S, BSN = B * S * N, CH = 64, PV = BSl * CH;
constexpr float LN_EPS = 1e-5f, EPS = 1e-8f;
}

__device__ float g_C[BSN], g_Km[BSN], g_gK[BSN];
__device__ __align__(16) float g_k[BN * D];
__device__ __align__(16) float g_v[BN * D];
__device__ float g_knorm[BN], g_logit[BN], g_atil[BN], g_inva[BN], g_rowM[BN];
__device__ float g_u[8 * BN];
__device__ float g_vs[9 * BSl];
__device__ float g_pv[2 * PV], g_pdv[2 * PV];
__device__ float g_pgn[B * CH], g_gn[B], g_amax[B], g_asum[B];
__device__ float g_slots[BSl * D], g_q[BSl * D], g_qn[BSl], g_btil[BSl], g_invb[BSl];
__device__ float g_upd[BSl * D], g_updp[B * 16 * S * D], g_posp[B * 16 * S * 2];

// ---- helpers ----
DI float blk_sum64(float v, float* sred, int tid) {
    sred[tid] = v; __syncthreads();
#pragma unroll
    for (int o = 32; o; o >>= 1) { if (tid < o) sred[tid] += sred[tid + o]; __syncthreads(); }
    float r = sred[0]; __syncthreads();
    return r;
}
DI void reduce7_store(const float* acc, float* out, int b, int chunk) {
    int tid = threadIdx.x, lane = tid & 31, w = tid >> 5;
    __shared__ float sm7[7][8];
#pragma unroll
    for (int s = 0; s < 7; s++) {
        float v = acc[s];
#pragma unroll
        for (int o = 16; o; o >>= 1) v += __shfl_down_sync(0xffffffffu, v, o);
        if (lane == 0) sm7[s][w] = v;
    }
    __syncthreads();
    if (tid < 7) {
        float t = 0.f;
#pragma unroll
        for (int ww = 0; ww < 8; ww++) t += sm7[tid][ww];
        out[(b * 7 + tid) * CH + chunk] = t;
    }
    __syncthreads();
}
DI void reduce1_store(float v, float* out) {
    int tid = threadIdx.x, lane = tid & 31, w = tid >> 5;
    __shared__ float s8[8];
#pragma unroll
    for (int o = 16; o; o >>= 1) v += __shfl_down_sync(0xffffffffu, v, o);
    if (lane == 0) s8[w] = v;
    __syncthreads();
    if (tid == 0) {
        float t = 0.f;
#pragma unroll
        for (int ww = 0; ww < 8; ww++) t += s8[ww];
        *out = t;
    }
    __syncthreads();
}
DI float dot64(const float4* __restrict__ w, const float* __restrict__ x) {
    float a0 = 0.f, a1 = 0.f, a2 = 0.f, a3 = 0.f;
#pragma unroll
    for (int i = 0; i < 16; i++) {
        float4 t = w[i];
        a0 += x[4 * i] * t.x; a1 += x[4 * i + 1] * t.y;
        a2 += x[4 * i + 2] * t.z; a3 += x[4 * i + 3] * t.w;
    }
    return (a0 + a1) + (a2 + a3);
}

// ---- kernels ----
__global__ void k_init(const float* __restrict__ mu, const float* __restrict__ sg,
                       const float* __restrict__ noise) {
    int i = blockIdx.x * 256 + threadIdx.x;
    if (i < BSl * D) {
        int d = i & 63;
        g_slots[i] = mu[d] + (fabsf(sg[d]) + EPS) * noise[i];
    }
    if (blockIdx.x == 0 && threadIdx.x < BSl) g_vs[threadIdx.x] = 1.f;
}

__global__ __launch_bounds__(128) void k_lnkv(
    const float* __restrict__ inp, const float* __restrict__ Wk, const float* __restrict__ Wv,
    const float* __restrict__ lng, const float* __restrict__ lnb,
    const float* __restrict__ wiw, const float* __restrict__ wib) {
    __shared__ float4 sWk[1024], sWv[1024];
    __shared__ float swi[64], sg[64], sb[64];
    int tid = threadIdx.x;
    const float4* wk4 = (const float4*)Wk; const float4* wv4 = (const float4*)Wv;
    for (int i = tid; i < 1024; i += 128) { sWk[i] = wk4[i]; sWv[i] = wv4[i]; }
    if (tid < 64) { swi[tid] = wiw[tid]; sg[tid] = lng[tid]; sb[tid] = lnb[tid]; }
    __syncthreads();
    int token = blockIdx.x * 128 + tid;
    float x[64];
    const float4* ip = (const float4*)(inp + (size_t)token * 64);
#pragma unroll
    for (int i = 0; i < 16; i++) {
        float4 t = ip[i];
        x[4 * i] = t.x; x[4 * i + 1] = t.y; x[4 * i + 2] = t.z; x[4 * i + 3] = t.w;
    }
    float m = 0.f;
#pragma unroll
    for (int i = 0; i < 64; i++) m += x[i];
    m *= (1.f / 64);
    float var = 0.f;
#pragma unroll
    for (int i = 0; i < 64; i++) { float dd = x[i] - m; var += dd * dd; }
    float inv = rsqrtf(var * (1.f / 64) + LN_EPS);
    float lg = 0.f;
#pragma unroll
    for (int i = 0; i < 64; i++) { x[i] = (x[i] - m) * inv * sg[i] + sb[i]; lg += x[i] * swi[i]; }
    g_logit[token] = lg + wib[0];
    float kn = 0.f;
    float4* kp = (float4*)(g_k + (size_t)token * 64);
#pragma unroll 2
    for (int j = 0; j < 64; j += 4) {
        float4 o;
        o.x = dot64(sWk + (j + 0) * 16, x); o.y = dot64(sWk + (j + 1) * 16, x);
        o.z = dot64(sWk + (j + 2) * 16, x); o.w = dot64(sWk + (j + 3) * 16, x);
        kn += o.x * o.x + o.y * o.y + o.z * o.z + o.w * o.w;
        kp[j >> 2] = o;
    }
    g_knorm[token] = kn;
    float4* vp = (float4*)(g_v + (size_t)token * 64);
#pragma unroll 2
    for (int j = 0; j < 64; j += 4) {
        float4 o;
        o.x = dot64(sWv + (j + 0) * 16, x); o.y = dot64(sWv + (j + 1) * 16, x);
        o.z = dot64(sWv + (j + 2) * 16, x); o.w = dot64(sWv + (j + 3) * 16, x);
        vp[j >> 2] = o;
    }
}

__global__ __launch_bounds__(1024) void k_areduce() {
    int b = blockIdx.x, tid = threadIdx.x;
    __shared__ float sm[1024];
    float m = -3.4e38f;
    for (int n = tid; n < N; n += 1024) m = fmaxf(m, g_logit[b * N + n]);
    sm[tid] = m; __syncthreads();
    for (int o = 512; o; o >>= 1) { if (tid < o) sm[tid] = fmaxf(sm[tid], sm[tid + o]); __syncthreads(); }
    float mm = sm[0]; __syncthreads();
    float s = 0.f;
    for (int n = tid; n < N; n += 1024) s += __expf(g_logit[b * N + n] - mm);
    sm[tid] = s; __syncthreads();
    for (int o = 512; o; o >>= 1) { if (tid < o) sm[tid] += sm[tid + o]; __syncthreads(); }
    if (tid == 0) { g_amax[b] = mm; g_asum[b] = sm[0]; }
}

__global__ void k_afin() {
    int i = blockIdx.x * 256 + threadIdx.x;
    int b = i >> 14;
    float at = __expf(g_logit[i] - g_amax[b]) * (7.f / g_asum[b]) + EPS;
    g_atil[i] = at; g_inva[i] = 1.f / at;
}

__global__ __launch_bounds__(64) void k_slotprep(
    const float* __restrict__ lng, const float* __restrict__ lnb,
    const float* __restrict__ Wq, const float* __restrict__ wsw, const float* __restrict__ wsb) {
    int b = blockIdx.x, tid = threadIdx.x;
    __shared__ float xln[7][64], sred[64], sl[7];
    float wsv = wsw[tid];
    for (int s = 0; s < 7; s++) {
        float v = g_slots[(b * 7 + s) * 64 + tid];
        float m = blk_sum64(v, sred, tid) * (1.f / 64);
        float dd = v - m;
        float var = blk_sum64(dd * dd, sred, tid) * (1.f / 64);
        float x = dd * rsqrtf(var + LN_EPS) * lng[tid] + lnb[tid];
        xln[s][tid] = x;
        float lg = blk_sum64(x * wsv, sred, tid);
        if (tid == 0) sl[s] = lg + wsb[0];
    }
    __syncthreads();
    if (tid == 0) {
        float mx = sl[0];
#pragma unroll
        for (int s = 1; s < 7; s++) mx = fmaxf(mx, sl[s]);
        float e[7], ss = 0.f;
#pragma unroll
        for (int s = 0; s < 7; s++) { e[s] = __expf(sl[s] - mx); ss += e[s]; }
#pragma unroll
        for (int s = 0; s < 7; s++) {
            float bt = e[s] / ss * 7.f + EPS;
            g_btil[b * 7 + s] = bt; g_invb[b * 7 + s] = 1.f / bt;
        }
    }
    __syncthreads();
    for (int s = 0; s < 7; s++) {
        float acc = 0.f;
        const float* wr = Wq + tid * 64;
#pragma unroll 8
        for (int j = 0; j < 64; j++) acc += xln[s][j] * wr[j];
        g_q[(b * 7 + s) * 64 + tid] = acc;
        float qn = blk_sum64(acc * acc, sred, tid);
        if (tid == 0) g_qn[b * 7 + s] = qn;
    }
}

__global__ __launch_bounds__(256) void k_buildC() {
    int b = blockIdx.x >> 6, chunk = blockIdx.x & 63, tid = threadIdx.x;
    __shared__ float sq[7][64], sqn[7];
    for (int i = tid; i < 448; i += 256) sq[i >> 6][i & 63] = g_q[b * 448 + i];
    if (tid < 7) sqn[tid] = g_qn[b * 7 + tid];
    __syncthreads();
    int n = chunk * 256 + tid;
    float kx[64];
    const float4* kp = (const float4*)(g_k + (size_t)(b * N + n) * 64);
#pragma unroll
    for (int i = 0; i < 16; i++) {
        float4 t = kp[i];
        kx[4 * i] = t.x; kx[4 * i + 1] = t.y; kx[4 * i + 2] = t.z; kx[4 * i + 3] = t.w;
    }
    float kn = g_knorm[b * N + n];
    int base = b * 7 * N + n;
#pragma unroll
    for (int s = 0; s < 7; s++) {
        float d0 = 0.f, d1 = 0.f;
#pragma unroll
        for (int j = 0; j < 64; j += 2) { d0 += kx[j] * sq[s][j]; d1 += kx[j + 1] * sq[s][j + 1]; }
        float sqd = kn + sqn[s] - 2.f * (d0 + d1);
        float c = sqrtf(fmaxf(sqd, 1e-12f));
        g_C[base + s * N] = c;
        g_Km[base + s * N] = __expf(-c);
    }
}

__global__ __launch_bounds__(256) void k_fwd(int pin, int pout, int vstore, int ustore, int apply) {
    int b = blockIdx.x >> 6, chunk = blockIdx.x & 63, tid = threadIdx.x;
    __shared__ float sv[7];
    if (pin >= 0) {
        if (tid < 224) {
            int s = tid >> 5, lane = tid & 31;
            const float* pp = g_pv + pin * PV + (b * 7 + s) * CH;
            float v = pp[lane] + pp[lane + 32];
#pragma unroll
            for (int o = 16; o; o >>= 1) v += __shfl_down_sync(0xffffffffu, v, o);
            if (lane == 0) {
                float vv = g_btil[b * 7 + s] / v;
                sv[s] = vv;
                if (vstore >= 0 && chunk == 0) g_vs[vstore * BSl + b * 7 + s] = vv;
            }
        }
    } else if (tid < 7) sv[tid] = 1.f;
    __syncthreads();
    int n = chunk * 256 + tid, base = b * 7 * N + n;
    float km[7];
    if (apply) {
        float ign = 1.f / g_gn[b];
#pragma unroll
        for (int s = 0; s < 7; s++) {
            float c = g_C[base + s * N] - g_gK[base + s * N] * ign;
            g_C[base + s * N] = c;
            km[s] = __expf(-c);
            g_Km[base + s * N] = km[s];
        }
    } else {
#pragma unroll
        for (int s = 0; s < 7; s++) km[s] = g_Km[base + s * N];
    }
    float den = 0.f;
#pragma unroll
    for (int s = 0; s < 7; s++) den += km[s] * sv[s];
    float u = g_atil[b * N + n] / den;
    if (ustore >= 0) g_u[ustore * BN + b * N + n] = u;
    float acc[7];
#pragma unroll
    for (int s = 0; s < 7; s++) acc[s] = km[s] * u;
    reduce7_store(acc, g_pv + pout * PV, b, chunk);
}

__global__ __launch_bounds__(256) void k_bwd_init() {
    int b = blockIdx.x >> 6, chunk = blockIdx.x & 63, tid = threadIdx.x;
    __shared__ float sv8[7];
    if (tid < 224) {
        int s = tid >> 5, lane = tid & 31;
        const float* pp = g_pv + PV + (b * 7 + s) * CH;
        float v = pp[lane] + pp[lane + 32];
#pragma unroll
        for (int o = 16; o; o >>= 1) v += __shfl_down_sync(0xffffffffu, v, o);
        if (lane == 0) {
            float vv = g_btil[b * 7 + s] / v;
            sv8[s] = vv;
            if (chunk == 0) g_vs[8 * BSl + b * 7 + s] = vv;
        }
    }
    __syncthreads();
    int n = chunk * 256 + tid, base = b * 7 * N + n;
    float u8 = g_u[7 * BN + b * N + n];
    float rowm = 0.f, acc[7];
#pragma unroll
    for (int s = 0; s < 7; s++) {
        float km = g_Km[base + s * N];
        float P = km * u8 * sv8[s];
        float gp = -(__logf(P + EPS) + P / (P + EPS));
        float mm = gp * P;
        g_gK[base + s * N] = -mm;
        rowm += mm; acc[s] = mm;
    }
    g_rowM[b * N + n] = rowm;
    reduce7_store(acc, g_pdv, b, chunk);
}

__global__ __launch_bounds__(256) void k_bwd(int t, int qin, int qout) {
    int b = blockIdx.x >> 6, chunk = blockIdx.x & 63, tid = threadIdx.x;
    __shared__ float sdD[7], svm1[7];
    if (tid < 224) {
        int s = tid >> 5, lane = tid & 31;
        const float* pp = g_pdv + qin * PV + (b * 7 + s) * CH;
        float v = pp[lane] + pp[lane + 32];
#pragma unroll
        for (int o = 16; o; o >>= 1) v += __shfl_down_sync(0xffffffffu, v, o);
        if (lane == 0) {
            float vt = g_vs[t * BSl + b * 7 + s];
            float fac = (t == 8) ? vt : vt * vt;
            sdD[s] = -v * fac * g_invb[b * 7 + s];
            svm1[s] = g_vs[(t - 1) * BSl + b * 7 + s];
        }
    }
    __syncthreads();
    int n = chunk * 256 + tid, base = b * 7 * N + n;
    float ut = g_u[(t - 1) * BN + b * N + n];
    float km[7];
#pragma unroll
    for (int s = 0; s < 7; s++) km[s] = g_Km[base + s * N];
    float du = 0.f;
#pragma unroll
    for (int s = 0; s < 7; s++) du += sdD[s] * km[s];
    if (t == 8) du += g_rowM[b * N + n] / ut;
    float dE = -du * ut * ut * g_inva[b * N + n];
    if (qout >= 0) {
        float acc[7];
#pragma unroll
        for (int s = 0; s < 7; s++) {
            g_gK[base + s * N] -= km[s] * (sdD[s] * ut + dE * svm1[s]);
            acc[s] = dE * km[s];
        }
        reduce7_store(acc, g_pdv + qout * PV, b, chunk);
    } else {
        float gsq = 0.f;
#pragma unroll
        for (int s = 0; s < 7; s++) {
            float g = g_gK[base + s * N] - km[s] * (sdD[s] * ut + dE * svm1[s]);
            g_gK[base + s * N] = g;
            gsq += g * g;
        }
        reduce1_store(gsq, &g_pgn[b * CH + chunk]);
    }
}

__global__ __launch_bounds__(64) void k_gn() {
    int b = blockIdx.x, tid = threadIdx.x;
    float v = g_pgn[b * CH + tid];
#pragma unroll
    for (int o = 16; o; o >>= 1) v += __shfl_down_sync(0xffffffffu, v, o);
    __shared__ float s2[2];
    if ((tid & 31) == 0) s2[tid >> 5] = v;
    __syncthreads();
    if (tid == 0) g_gn[b] = sqrtf(s2[0] + s2[1]) + EPS;
}

__global__ __launch_bounds__(256) void k_Pout(float* __restrict__ outa) {
    int b = blockIdx.x >> 6, chunk = blockIdx.x & 63, tid = threadIdx.x;
    __shared__ float sv[7];
    if (tid < 224) {
        int s = tid >> 5, lane = tid & 31;
        const float* pp = g_pv + PV + (b * 7 + s) * CH;
        float v = pp[lane] + pp[lane + 32];
#pragma unroll
        for (int o = 16; o; o >>= 1) v += __shfl_down_sync(0xffffffffu, v, o);
        if (lane == 0) sv[s] = g_btil[b * 7 + s] / v;
    }
    __syncthreads();
    int n = chunk * 256 + tid, base = b * 7 * N + n;
    float u = g_u[b * N + n];
#pragma unroll
    for (int s = 0; s < 7; s++) outa[base + s * N] = g_Km[base + s * N] * u * sv[s];
}

__global__ __launch_bounds__(224) void k_upd(const float* __restrict__ outa) {
    int b = blockIdx.x >> 4, chunk = blockIdx.x & 15, tid = threadIdx.x;
    int s = tid >> 5, d2 = tid & 31;
    const float* Pp = outa + (size_t)(b * 7 + s) * N + chunk * 1024;
    const float2* v2 = (const float2*)g_v + ((size_t)b * N + chunk * 1024) * 32 + d2;
    float ax = 0.f, ay = 0.f, px = 0.f, py = 0.f;
    for (int i = 0; i < 1024; i++) {
        float p = Pp[i];
        float2 vv = v2[(size_t)i * 32];
        ax += p * vv.x; ay += p * vv.y;
        if (d2 == 0) {
            int n = chunk * 1024 + i;
            px += p * ((n & 127) * (1.f / 127.f));
            py += p * ((n >> 7) * (1.f / 127.f));
        }
    }
    int ob = ((b * 16 + chunk) * 7 + s) * 64 + d2 * 2;
    g_updp[ob] = ax; g_updp[ob + 1] = ay;
    if (d2 == 0) {
        int pb = ((b * 16 + chunk) * 7 + s) * 2;
        g_posp[pb] = px; g_posp[pb + 1] = py;
    }
}

__global__ __launch_bounds__(64) void k_updfin(float* __restrict__ outp) {
    int bs = blockIdx.x, tid = threadIdx.x;
    int b = bs / 7, s = bs % 7;
    float acc = 0.f;
#pragma unroll
    for (int c = 0; c < 16; c++) acc += g_updp[((b * 16 + c) * 7 + s) * 64 + tid];
    g_upd[bs * 64 + tid] = acc;
    if (tid < 2) {
        float p = 0.f;
#pragma unroll
        for (int c = 0; c < 16; c++) p += g_posp[((b * 16 + c) * 7 + s) * 2 + tid];
        outp[bs * 2 + tid] = p;
    }
}

__global__ __launch_bounds__(64) void k_gruff(
    const float* __restrict__ Wih, const float* __restrict__ Whh,
    const float* __restrict__ bih, const float* __restrict__ bhh,
    const float* __restrict__ f1w, const float* __restrict__ f1b,
    const float* __restrict__ f2w, const float* __restrict__ f2b,
    const float* __restrict__ lng, const float* __restrict__ lnb,
    float* __restrict__ outs, int last) {
    int bs = blockIdx.x, tid = threadIdx.x;
    __shared__ float su[64], sp[64], sx[64], shid[128], sred[64];
    su[tid] = g_upd[bs * 64 + tid];
    sp[tid] = g_slots[bs * 64 + tid];
    __syncthreads();
    float ir = bih[tid], iz = bih[64 + tid], inn = bih[128 + tid];
    float hr = bhh[tid], hz = bhh[64 + tid], hn = bhh[128 + tid];
#pragma unroll 4
    for (int d = 0; d < 64; d++) {
        float uu = su[d], pp = sp[d];
        ir += Wih[tid * 64 + d] * uu;
        iz += Wih[(64 + tid) * 64 + d] * uu;
        inn += Wih[(128 + tid) * 64 + d] * uu;
        hr += Whh[tid * 64 + d] * pp;
        hz += Whh[(64 + tid) * 64 + d] * pp;
        hn += Whh[(128 + tid) * 64 + d] * pp;
    }
    float r = 1.f / (1.f + expf(-(ir + hr)));
    float z = 1.f / (1.f + expf(-(iz + hz)));
    float nn = tanhf(inn + r * hn);
    float h = (1.f - z) * nn + z * sp[tid];
    float m = blk_sum64(h, sred, tid) * (1.f / 64);
    float dd = h - m;
    float var = blk_sum64(dd * dd, sred, tid) * (1.f / 64);
    sx[tid] = dd * rsqrtf(var + LN_EPS) * lng[tid] + lnb[tid];
    __syncthreads();
#pragma unroll
    for (int jj = 0; jj < 2; jj++) {
        int j = tid + jj * 64;
        float a = f1b[j];
#pragma unroll 4
        for (int d = 0; d < 64; d++) a += sx[d] * f1w[j * 64 + d];
        shid[j] = fmaxf(a, 0.f);
    }
    __syncthreads();
    float o = f2b[tid];
#pragma unroll 4
    for (int j = 0; j < 128; j++) o += shid[j] * f2w[tid * 128 + j];
    float ns = h + o;
    g_slots[bs * 64 + tid] = ns;
    if (last) outs[bs * 64 + tid] = ns;
}

// ---- host ----
extern "C" void kernel_launch(void* const* d_in, const int* in_sizes, int n_in,
                              void* d_out, int out_size) {
    const float* inp  = (const float*)d_in[0];
    const float* noi  = (const float*)d_in[1];
    const float* mu   = (const float*)d_in[2];
    const float* sig  = (const float*)d_in[3];
    const float* Wq   = (const float*)d_in[4];
    const float* Wk   = (const float*)d_in[5];
    const float* Wv   = (const float*)d_in[6];
    const float* Wih  = (const float*)d_in[7];
    const float* Whh  = (const float*)d_in[8];
    const float* bih  = (const float*)d_in[9];
    const float* bhh  = (const float*)d_in[10];
    const float* f1w  = (const float*)d_in[11];
    const float* f1b  = (const float*)d_in[12];
    const float* f2w  = (const float*)d_in[13];
    const float* f2b  = (const float*)d_in[14];
    const float* ling = (const float*)d_in[15];
    const float* linb = (const float*)d_in[16];
    const float* lsg  = (const float*)d_in[17];
    const float* lsb  = (const float*)d_in[18];
    const float* lfg  = (const float*)d_in[19];
    const float* lfb  = (const float*)d_in[20];
    const float* wiw  = (const float*)d_in[21];
    const float* wib  = (const float*)d_in[22];
    const float* wsw  = (const float*)d_in[23];
    const float* wsb  = (const float*)d_in[24];
    float* out = (float*)d_out;
    float* out_slots = out;
    float* out_pos   = out + BSl * D;
    float* out_attn  = out + BSl * D + BSl * 2;

    k_init<<<56, 256>>>(mu, sig, noi);
    k_lnkv<<<BN / 128, 128>>>(inp, Wk, Wv, ling, linb, wiw, wib);
    k_areduce<<<B, 1024>>>();
    k_afin<<<BN / 256, 256>>>();

    for (int it = 0; it < 3; it++) {
        k_slotprep<<<B, 64>>>(lsg, lsb, Wq, wsw, wsb);
        k_buildC<<<B * CH, 256>>>();
        for (int e = 0; e < 4; e++) {
            k_fwd<<<B * CH, 256>>>(-1, 0, -1, 0, e > 0 ? 1 : 0);
            for (int t = 2; t <= 8; t++)
                k_fwd<<<B * CH, 256>>>((t - 2) & 1, (t - 1) & 1, t - 1, t - 1, 0);
            k_bwd_init<<<B * CH, 256>>>();
            for (int t = 8; t >= 1; t--)
                k_bwd<<<B * CH, 256>>>(t, (8 - t) & 1, t == 1 ? -1 : ((9 - t) & 1));
            k_gn<<<B, 64>>>();
        }
        k_fwd<<<B * CH, 256>>>(-1, 0, -1, -1, 1);
        for (int t = 2; t <= 16; t++)
            k_fwd<<<B * CH, 256>>>((t - 2) & 1, (t - 1) & 1, -1, t == 16 ? 0 : -1, 0);
        k_Pout<<<B * CH, 256>>>(out_attn);
        k_upd<<<B * 16, 224>>>(out_attn);
        k_updfin<<<BSl, 64>>>(out_pos);
        k_gruff<<<BSl, 64>>>(Wih, Whh, bih, bhh, f1w, f1b, f2w, f2b, lfg, lfb,
                             out_slots, it == 2 ? 1 : 0);
    }
}

// round 10
// speedup vs baseline: 1.0471x; 1.0471x over previous
#include <cuda_runtime.h>
#define DI __device__ __forceinline__

namespace {
constexpr int B = 32, N = 16384, S = 7, D = 64;
constexpr int BN = B * N, BSl = B * S, BSN = B * S * N;
constexpr int NCH = 8, NBLK = B * NCH, TOKB = N / NCH;   // fused kernel: 256 blocks, 2048 tokens each
constexpr int PV2 = B * S * NCH;
constexpr float LN_EPS = 1e-5f, EPS = 1e-8f;
}

__device__ float g_C[BSN], g_Km[BSN], g_gK[BSN];
__device__ __align__(16) float g_k[BN * D];
__device__ __align__(16) float g_v[BN * D];
__device__ float g_knorm[BN], g_logit[BN], g_atil[BN], g_inva[BN];
__device__ float g_u[8 * BN];
__device__ float g_pv2[2 * PV2], g_pdv2[2 * PV2], g_pgn2[NBLK];
__device__ unsigned g_barcnt;
__device__ float g_amax[B], g_asum[B];
__device__ float g_slots[BSl * D], g_q[BSl * D], g_qn[BSl], g_btil[BSl], g_invb[BSl];
__device__ float g_upd[BSl * D], g_updp[B * 16 * S * D], g_posp[B * 16 * S * 2];

// ---- helpers ----
DI float blk_sum64(float v, float* sred, int tid) {
    sred[tid] = v; __syncthreads();
#pragma unroll
    for (int o = 32; o; o >>= 1) { if (tid < o) sred[tid] += sred[tid + o]; __syncthreads(); }
    float r = sred[0]; __syncthreads();
    return r;
}
DI float dot64(const float4* __restrict__ w, const float* __restrict__ x) {
    float a0 = 0.f, a1 = 0.f, a2 = 0.f, a3 = 0.f;
#pragma unroll
    for (int i = 0; i < 16; i++) {
        float4 t = w[i];
        a0 += x[4 * i] * t.x; a1 += x[4 * i + 1] * t.y;
        a2 += x[4 * i + 2] * t.z; a3 += x[4 * i + 3] * t.w;
    }
    return (a0 + a1) + (a2 + a3);
}

// grid barrier: monotonic counter, reset by k_slotprep before each k_mesh launch
DI void gbar(unsigned goal) {
    __syncthreads();
    if (threadIdx.x == 0) {
        __threadfence();
        atomicAdd(&g_barcnt, 1u);
        volatile unsigned* p = &g_barcnt;
        while (*p < goal) __nanosleep(64);
        __threadfence();
    }
    __syncthreads();
}

// block-reduce 7 accumulators (8 warps) -> per-(b,s,chunk) partials, fixed order
DI void red7(const float* acc, float* outbase, int b, int c) {
    int tid = threadIdx.x, lane = tid & 31, w = tid >> 5;
    __shared__ float sm7[7][8];
#pragma unroll
    for (int s = 0; s < 7; s++) {
        float v = acc[s];
#pragma unroll
        for (int o = 16; o; o >>= 1) v += __shfl_down_sync(0xffffffffu, v, o);
        if (lane == 0) sm7[s][w] = v;
    }
    __syncthreads();
    if (tid < 7) {
        float t = 0.f;
#pragma unroll
        for (int ww = 0; ww < 8; ww++) t += sm7[tid][ww];
        outbase[(b * 7 + tid) * NCH + c] = t;
    }
    __syncthreads();
}
DI void red1(float v, float* out) {
    int tid = threadIdx.x, lane = tid & 31, w = tid >> 5;
    __shared__ float s8[8];
#pragma unroll
    for (int o = 16; o; o >>= 1) v += __shfl_down_sync(0xffffffffu, v, o);
    if (lane == 0) s8[w] = v;
    __syncthreads();
    if (tid == 0) {
        float t = 0.f;
#pragma unroll
        for (int ww = 0; ww < 8; ww++) t += s8[ww];
        *out = t;
    }
    __syncthreads();
}
// reduce chunk partials -> v = btil / sum; optionally store into smem v-history
DI void vred(const float* pbase, int b, int storeidx, float* svh, float* sv, const float* sbt) {
    int tid = threadIdx.x;
    if (tid < 7) {
        float sum = 0.f;
#pragma unroll
        for (int c2 = 0; c2 < NCH; c2++) sum += __ldcg(&pbase[(b * 7 + tid) * NCH + c2]);
        float vv = sbt[tid] / sum;
        sv[tid] = vv;
        if (storeidx >= 0) svh[storeidx * 7 + tid] = vv;
    }
    __syncthreads();
}

// ---- kernels ----
__global__ void k_init(const float* __restrict__ mu, const float* __restrict__ sg,
                       const float* __restrict__ noise) {
    int i = blockIdx.x * 256 + threadIdx.x;
    if (i < BSl * D) {
        int d = i & 63;
        g_slots[i] = mu[d] + (fabsf(sg[d]) + EPS) * noise[i];
    }
}

__global__ __launch_bounds__(128) void k_lnkv(
    const float* __restrict__ inp, const float* __restrict__ Wk, const float* __restrict__ Wv,
    const float* __restrict__ lng, const float* __restrict__ lnb,
    const float* __restrict__ wiw, const float* __restrict__ wib) {
    __shared__ float4 sWk[1024], sWv[1024];
    __shared__ float swi[64], sg[64], sb[64];
    int tid = threadIdx.x;
    const float4* wk4 = (const float4*)Wk; const float4* wv4 = (const float4*)Wv;
    for (int i = tid; i < 1024; i += 128) { sWk[i] = wk4[i]; sWv[i] = wv4[i]; }
    if (tid < 64) { swi[tid] = wiw[tid]; sg[tid] = lng[tid]; sb[tid] = lnb[tid]; }
    __syncthreads();
    int token = blockIdx.x * 128 + tid;
    float x[64];
    const float4* ip = (const float4*)(inp + (size_t)token * 64);
#pragma unroll
    for (int i = 0; i < 16; i++) {
        float4 t = ip[i];
        x[4 * i] = t.x; x[4 * i + 1] = t.y; x[4 * i + 2] = t.z; x[4 * i + 3] = t.w;
    }
    float m = 0.f;
#pragma unroll
    for (int i = 0; i < 64; i++) m += x[i];
    m *= (1.f / 64);
    float var = 0.f;
#pragma unroll
    for (int i = 0; i < 64; i++) { float dd = x[i] - m; var += dd * dd; }
    float inv = rsqrtf(var * (1.f / 64) + LN_EPS);
    float lg = 0.f;
#pragma unroll
    for (int i = 0; i < 64; i++) { x[i] = (x[i] - m) * inv * sg[i] + sb[i]; lg += x[i] * swi[i]; }
    g_logit[token] = lg + wib[0];
    float kn = 0.f;
    float4* kp = (float4*)(g_k + (size_t)token * 64);
#pragma unroll 2
    for (int j = 0; j < 64; j += 4) {
        float4 o;
        o.x = dot64(sWk + (j + 0) * 16, x); o.y = dot64(sWk + (j + 1) * 16, x);
        o.z = dot64(sWk + (j + 2) * 16, x); o.w = dot64(sWk + (j + 3) * 16, x);
        kn += o.x * o.x + o.y * o.y + o.z * o.z + o.w * o.w;
        kp[j >> 2] = o;
    }
    g_knorm[token] = kn;
    float4* vp = (float4*)(g_v + (size_t)token * 64);
#pragma unroll 2
    for (int j = 0; j < 64; j += 4) {
        float4 o;
        o.x = dot64(sWv + (j + 0) * 16, x); o.y = dot64(sWv + (j + 1) * 16, x);
        o.z = dot64(sWv + (j + 2) * 16, x); o.w = dot64(sWv + (j + 3) * 16, x);
        vp[j >> 2] = o;
    }
}

__global__ __launch_bounds__(1024) void k_areduce() {
    int b = blockIdx.x, tid = threadIdx.x;
    __shared__ float sm[1024];
    float m = -3.4e38f;
    for (int n = tid; n < N; n += 1024) m = fmaxf(m, g_logit[b * N + n]);
    sm[tid] = m; __syncthreads();
    for (int o = 512; o; o >>= 1) { if (tid < o) sm[tid] = fmaxf(sm[tid], sm[tid + o]); __syncthreads(); }
    float mm = sm[0]; __syncthreads();
    float s = 0.f;
    for (int n = tid; n < N; n += 1024) s += __expf(g_logit[b * N + n] - mm);
    sm[tid] = s; __syncthreads();
    for (int o = 512; o; o >>= 1) { if (tid < o) sm[tid] += sm[tid + o]; __syncthreads(); }
    if (tid == 0) { g_amax[b] = mm; g_asum[b] = sm[0]; }
}

__global__ void k_afin() {
    int i = blockIdx.x * 256 + threadIdx.x;
    int b = i >> 14;
    float at = __expf(g_logit[i] - g_amax[b]) * (7.f / g_asum[b]) + EPS;
    g_atil[i] = at; g_inva[i] = 1.f / at;
}

__global__ __launch_bounds__(64) void k_slotprep(
    const float* __restrict__ lng, const float* __restrict__ lnb,
    const float* __restrict__ Wq, const float* __restrict__ wsw, const float* __restrict__ wsb) {
    int b = blockIdx.x, tid = threadIdx.x;
    if (b == 0 && tid == 0) g_barcnt = 0;   // reset grid barrier for the following k_mesh
    __shared__ float xln[7][64], sred[64], sl[7];
    float wsv = wsw[tid];
    for (int s = 0; s < 7; s++) {
        float v = g_slots[(b * 7 + s) * 64 + tid];
        float m = blk_sum64(v, sred, tid) * (1.f / 64);
        float dd = v - m;
        float var = blk_sum64(dd * dd, sred, tid) * (1.f / 64);
        float x = dd * rsqrtf(var + LN_EPS) * lng[tid] + lnb[tid];
        xln[s][tid] = x;
        float lg = blk_sum64(x * wsv, sred, tid);
        if (tid == 0) sl[s] = lg + wsb[0];
    }
    __syncthreads();
    if (tid == 0) {
        float mx = sl[0];
#pragma unroll
        for (int s = 1; s < 7; s++) mx = fmaxf(mx, sl[s]);
        float e[7], ss = 0.f;
#pragma unroll
        for (int s = 0; s < 7; s++) { e[s] = __expf(sl[s] - mx); ss += e[s]; }
#pragma unroll
        for (int s = 0; s < 7; s++) {
            float bt = e[s] / ss * 7.f + EPS;
            g_btil[b * 7 + s] = bt; g_invb[b * 7 + s] = 1.f / bt;
        }
    }
    __syncthreads();
    for (int s = 0; s < 7; s++) {
        float acc = 0.f;
        const float* wr = Wq + tid * 64;
#pragma unroll 8
        for (int j = 0; j < 64; j++) acc += xln[s][j] * wr[j];
        g_q[(b * 7 + s) * 64 + tid] = acc;
        float qn = blk_sum64(acc * acc, sred, tid);
        if (tid == 0) g_qn[b * 7 + s] = qn;
    }
}

__global__ __launch_bounds__(256) void k_buildC() {
    int b = blockIdx.x >> 6, chunk = blockIdx.x & 63, tid = threadIdx.x;
    __shared__ float sq[7][64], sqn[7];
    for (int i = tid; i < 448; i += 256) sq[i >> 6][i & 63] = g_q[b * 448 + i];
    if (tid < 7) sqn[tid] = g_qn[b * 7 + tid];
    __syncthreads();
    int n = chunk * 256 + tid;
    float kx[64];
    const float4* kp = (const float4*)(g_k + (size_t)(b * N + n) * 64);
#pragma unroll
    for (int i = 0; i < 16; i++) {
        float4 t = kp[i];
        kx[4 * i] = t.x; kx[4 * i + 1] = t.y; kx[4 * i + 2] = t.z; kx[4 * i + 3] = t.w;
    }
    float kn = g_knorm[b * N + n];
    int base = b * 7 * N + n;
#pragma unroll
    for (int s = 0; s < 7; s++) {
        float d0 = 0.f, d1 = 0.f;
#pragma unroll
        for (int j = 0; j < 64; j += 2) { d0 += kx[j] * sq[s][j]; d1 += kx[j + 1] * sq[s][j + 1]; }
        float sqd = kn + sqn[s] - 2.f * (d0 + d1);
        float c = sqrtf(fmaxf(sqd, 1e-12f));
        g_C[base + s * N] = c;
        g_Km[base + s * N] = __expf(-c);
    }
}

// ===== fused mesh + sinkhorn + Pout: one launch per slot-attention iteration =====
__global__ __launch_bounds__(256, 2) void k_mesh(float* __restrict__ outa) {
    int b = blockIdx.x >> 3, c = blockIdx.x & 7, tid = threadIdx.x;
    int gb = b * N;
    int cb = b * 7 * N;
    int tok0 = c * TOKB;
    __shared__ float sv[7], svh[9 * 7], sbt[7], sib[7], ssd[7], ssv[7], sgn[1];
    if (tid < 7) {
        sbt[tid] = g_btil[b * 7 + tid];
        sib[tid] = g_invb[b * 7 + tid];
        svh[tid] = 1.f;                     // v_0 = 1
    }
    __syncthreads();
    unsigned nbar = 0;
    float rowm[8];                           // rowM in mesh-bwd; re-used as u_16 in final phase

    for (int e = 0; e < 5; e++) {            // e=0..3 mesh grad evals, e=4 final 16-iter sinkhorn
        const bool mesh = (e < 4);
        const int tmax = mesh ? 8 : 16;
        // ---- forward iterations ----
        for (int t = 1; t <= tmax; t++) {
            if (t == 1) {
                if (tid < 7) sv[tid] = 1.f;
                __syncthreads();
            } else {
                vred(g_pv2 + ((t - 2) & 1) * PV2, b, mesh ? (t - 1) : -1, svh, sv, sbt);
            }
            float svr[7];
#pragma unroll
            for (int s = 0; s < 7; s++) svr[s] = sv[s];
            float ign = (t == 1 && e > 0) ? (1.f / sgn[0]) : 0.f;
            float acc[7] = {0.f, 0.f, 0.f, 0.f, 0.f, 0.f, 0.f};
            for (int j = 0; j < 8; j++) {
                int n = tok0 + j * 256 + tid;
                int idx = cb + n;
                float km[7];
                if (t == 1 && e > 0) {       // apply normalized gradient step, rebuild Km
#pragma unroll
                    for (int s = 0; s < 7; s++) {
                        float c0 = g_C[idx + s * N] - g_gK[idx + s * N] * ign;
                        g_C[idx + s * N] = c0;
                        km[s] = __expf(-c0);
                        g_Km[idx + s * N] = km[s];
                    }
                } else {
#pragma unroll
                    for (int s = 0; s < 7; s++) km[s] = g_Km[idx + s * N];
                }
                float den = 0.f;
#pragma unroll
                for (int s = 0; s < 7; s++) den += km[s] * svr[s];
                float u = g_atil[gb + n] / den;
                if (mesh) g_u[(t - 1) * BN + gb + n] = u;
                else if (t == tmax) rowm[j] = u;          // keep u_16 in regs
#pragma unroll
                for (int s = 0; s < 7; s++) acc[s] += km[s] * u;
            }
            red7(acc, g_pv2 + ((t - 1) & 1) * PV2, b, c);
            gbar(++nbar * NBLK);
        }
        if (!mesh) break;
        // ---- backward init (t=8): M = gP*P, gK = -M, rowM, colsum partials ----
        vred(g_pv2 + PV2, b, 8, svh, sv, sbt);
        {
            float svr[7];
#pragma unroll
            for (int s = 0; s < 7; s++) svr[s] = sv[s];
            float acc[7] = {0.f, 0.f, 0.f, 0.f, 0.f, 0.f, 0.f};
            for (int j = 0; j < 8; j++) {
                int n = tok0 + j * 256 + tid;
                int idx = cb + n;
                float u8 = g_u[7 * BN + gb + n];
                float rm = 0.f;
#pragma unroll
                for (int s = 0; s < 7; s++) {
                    float km = g_Km[idx + s * N];
                    float P = km * u8 * svr[s];
                    float gp = -(__logf(P + EPS) + P / (P + EPS));
                    float mm = gp * P;
                    g_gK[idx + s * N] = -mm;
                    rm += mm; acc[s] += mm;
                }
                rowm[j] = rm;
            }
            red7(acc, g_pdv2, b, c);
            gbar(++nbar * NBLK);
        }
        // ---- backward adjoint chain t=8..1 ----
        for (int t = 8; t >= 1; t--) {
            int qin = (8 - t) & 1;
            if (tid < 7) {
                float dv = 0.f;
#pragma unroll
                for (int c2 = 0; c2 < NCH; c2++)
                    dv += __ldcg(&g_pdv2[qin * PV2 + (b * 7 + tid) * NCH + c2]);
                float vt = svh[t * 7 + tid];
                float fac = (t == 8) ? vt : vt * vt;
                ssd[tid] = -dv * fac * sib[tid];
                ssv[tid] = svh[(t - 1) * 7 + tid];
            }
            __syncthreads();
            float sdr[7], svm[7];
#pragma unroll
            for (int s = 0; s < 7; s++) { sdr[s] = ssd[s]; svm[s] = ssv[s]; }
            float acc[7] = {0.f, 0.f, 0.f, 0.f, 0.f, 0.f, 0.f};
            float gsq = 0.f;
            for (int j = 0; j < 8; j++) {
                int n = tok0 + j * 256 + tid;
                int idx = cb + n;
                float ut = g_u[(t - 1) * BN + gb + n];
                float km[7];
#pragma unroll
                for (int s = 0; s < 7; s++) km[s] = g_Km[idx + s * N];
                float du = 0.f;
#pragma unroll
                for (int s = 0; s < 7; s++) du += sdr[s] * km[s];
                if (t == 8) du += rowm[j] / ut;
                float dE = -du * ut * ut * g_inva[gb + n];
                if (t > 1) {
#pragma unroll
                    for (int s = 0; s < 7; s++) {
                        g_gK[idx + s * N] -= km[s] * (sdr[s] * ut + dE * svm[s]);
                        acc[s] += dE * km[s];
                    }
                } else {
#pragma unroll
                    for (int s = 0; s < 7; s++) {
                        float g = g_gK[idx + s * N] - km[s] * (sdr[s] * ut + dE * svm[s]);
                        g_gK[idx + s * N] = g;
                        gsq += g * g;
                    }
                }
            }
            if (t > 1) red7(acc, g_pdv2 + ((9 - t) & 1) * PV2, b, c);
            else red1(gsq, &g_pgn2[b * NCH + c]);
            gbar(++nbar * NBLK);
        }
        // ---- grad norm for this batch ----
        if (tid == 0) {
            float sum = 0.f;
#pragma unroll
            for (int c2 = 0; c2 < NCH; c2++) sum += __ldcg(&g_pgn2[b * NCH + c2]);
            sgn[0] = sqrtf(sum) + EPS;
        }
        __syncthreads();
    }
    // ---- P output: v_16 from final partials (parity 1), u_16 in rowm ----
    vred(g_pv2 + PV2, b, -1, svh, sv, sbt);
    float svr[7];
#pragma unroll
    for (int s = 0; s < 7; s++) svr[s] = sv[s];
    for (int j = 0; j < 8; j++) {
        int n = tok0 + j * 256 + tid;
        int idx = cb + n;
        float u = rowm[j];
#pragma unroll
        for (int s = 0; s < 7; s++) outa[idx + s * N] = g_Km[idx + s * N] * u * svr[s];
    }
}

__global__ __launch_bounds__(224) void k_upd(const float* __restrict__ outa) {
    int b = blockIdx.x >> 4, chunk = blockIdx.x & 15, tid = threadIdx.x;
    int s = tid >> 5, d2 = tid & 31;
    const float* Pp = outa + (size_t)(b * 7 + s) * N + chunk * 1024;
    const float2* v2 = (const float2*)g_v + ((size_t)b * N + chunk * 1024) * 32 + d2;
    float ax = 0.f, ay = 0.f, px = 0.f, py = 0.f;
    for (int i = 0; i < 1024; i++) {
        float p = Pp[i];
        float2 vv = v2[(size_t)i * 32];
        ax += p * vv.x; ay += p * vv.y;
        if (d2 == 0) {
            int n = chunk * 1024 + i;
            px += p * ((n & 127) * (1.f / 127.f));
            py += p * ((n >> 7) * (1.f / 127.f));
        }
    }
    int ob = ((b * 16 + chunk) * 7 + s) * 64 + d2 * 2;
    g_updp[ob] = ax; g_updp[ob + 1] = ay;
    if (d2 == 0) {
        int pb = ((b * 16 + chunk) * 7 + s) * 2;
        g_posp[pb] = px; g_posp[pb + 1] = py;
    }
}

__global__ __launch_bounds__(64) void k_updfin(float* __restrict__ outp) {
    int bs = blockIdx.x, tid = threadIdx.x;
    int b = bs / 7, s = bs % 7;
    float acc = 0.f;
#pragma unroll
    for (int c = 0; c < 16; c++) acc += g_updp[((b * 16 + c) * 7 + s) * 64 + tid];
    g_upd[bs * 64 + tid] = acc;
    if (tid < 2) {
        float p = 0.f;
#pragma unroll
        for (int c = 0; c < 16; c++) p += g_posp[((b * 16 + c) * 7 + s) * 2 + tid];
        outp[bs * 2 + tid] = p;
    }
}

__global__ __launch_bounds__(64) void k_gruff(
    const float* __restrict__ Wih, const float* __restrict__ Whh,
    const float* __restrict__ bih, const float* __restrict__ bhh,
    const float* __restrict__ f1w, const float* __restrict__ f1b,
    const float* __restrict__ f2w, const float* __restrict__ f2b,
    const float* __restrict__ lng, const float* __restrict__ lnb,
    float* __restrict__ outs, int last) {
    int bs = blockIdx.x, tid = threadIdx.x;
    __shared__ float su[64], sp[64], sx[64], shid[128], sred[64];
    su[tid] = g_upd[bs * 64 + tid];
    sp[tid] = g_slots[bs * 64 + tid];
    __syncthreads();
    float ir = bih[tid], iz = bih[64 + tid], inn = bih[128 + tid];
    float hr = bhh[tid], hz = bhh[64 + tid], hn = bhh[128 + tid];
#pragma unroll 4
    for (int d = 0; d < 64; d++) {
        float uu = su[d], pp = sp[d];
        ir += Wih[tid * 64 + d] * uu;
        iz += Wih[(64 + tid) * 64 + d] * uu;
        inn += Wih[(128 + tid) * 64 + d] * uu;
        hr += Whh[tid * 64 + d] * pp;
        hz += Whh[(64 + tid) * 64 + d] * pp;
        hn += Whh[(128 + tid) * 64 + d] * pp;
    }
    float r = 1.f / (1.f + expf(-(ir + hr)));
    float z = 1.f / (1.f + expf(-(iz + hz)));
    float nn = tanhf(inn + r * hn);
    float h = (1.f - z) * nn + z * sp[tid];
    float m = blk_sum64(h, sred, tid) * (1.f / 64);
    float dd = h - m;
    float var = blk_sum64(dd * dd, sred, tid) * (1.f / 64);
    sx[tid] = dd * rsqrtf(var + LN_EPS) * lng[tid] + lnb[tid];
    __syncthreads();
#pragma unroll
    for (int jj = 0; jj < 2; jj++) {
        int j = tid + jj * 64;
        float a = f1b[j];
#pragma unroll 4
        for (int d = 0; d < 64; d++) a += sx[d] * f1w[j * 64 + d];
        shid[j] = fmaxf(a, 0.f);
    }
    __syncthreads();
    float o = f2b[tid];
#pragma unroll 4
    for (int j = 0; j < 128; j++) o += shid[j] * f2w[tid * 128 + j];
    float ns = h + o;
    g_slots[bs * 64 + tid] = ns;
    if (last) outs[bs * 64 + tid] = ns;
}

// ---- host ----
extern "C" void kernel_launch(void* const* d_in, const int* in_sizes, int n_in,
                              void* d_out, int out_size) {
    const float* inp  = (const float*)d_in[0];
    const float* noi  = (const float*)d_in[1];
    const float* mu   = (const float*)d_in[2];
    const float* sig  = (const float*)d_in[3];
    const float* Wq   = (const float*)d_in[4];
    const float* Wk   = (const float*)d_in[5];
    const float* Wv   = (const float*)d_in[6];
    const float* Wih  = (const float*)d_in[7];
    const float* Whh  = (const float*)d_in[8];
    const float* bih  = (const float*)d_in[9];
    const float* bhh  = (const float*)d_in[10];
    const float* f1w  = (const float*)d_in[11];
    const float* f1b  = (const float*)d_in[12];
    const float* f2w  = (const float*)d_in[13];
    const float* f2b  = (const float*)d_in[14];
    const float* ling = (const float*)d_in[15];
    const float* linb = (const float*)d_in[16];
    const float* lsg  = (const float*)d_in[17];
    const float* lsb  = (const float*)d_in[18];
    const float* lfg  = (const float*)d_in[19];
    const float* lfb  = (const float*)d_in[20];
    const float* wiw  = (const float*)d_in[21];
    const float* wib  = (const float*)d_in[22];
    const float* wsw  = (const float*)d_in[23];
    const float* wsb  = (const float*)d_in[24];
    float* out = (float*)d_out;
    float* out_slots = out;
    float* out_pos   = out + BSl * D;
    float* out_attn  = out + BSl * D + BSl * 2;

    k_init<<<56, 256>>>(mu, sig, noi);
    k_lnkv<<<BN / 128, 128>>>(inp, Wk, Wv, ling, linb, wiw, wib);
    k_areduce<<<B, 1024>>>();
    k_afin<<<BN / 256, 256>>>();

    for (int it = 0; it < 3; it++) {
        k_slotprep<<<B, 64>>>(lsg, lsb, Wq, wsw, wsb);
        k_buildC<<<B * 64, 256>>>();
        k_mesh<<<NBLK, 256>>>(out_attn);
        k_upd<<<B * 16, 224>>>(out_attn);
        k_updfin<<<BSl, 64>>>(out_pos);
        k_gruff<<<BSl, 64>>>(Wih, Whh, bih, bhh, f1w, f1b, f2w, f2b, lfg, lfb,
                             out_slots, it == 2 ? 1 : 0);
    }
}

// round 11
// speedup vs baseline: 1.3785x; 1.3164x over previous
#include <cuda_runtime.h>
#define DI __device__ __forceinline__

namespace {
constexpr int B = 32, N = 16384, S = 7, D = 64;
constexpr int BN = B * N, BSl = B * S, BSN = B * S * N;
constexpr int NCH = 16, NBLK = B * NCH, TOKB = N / NCH;  // 512 blocks, 1024 tokens each
constexpr int PV2 = B * S * NCH;
constexpr float LN_EPS = 1e-5f, EPS = 1e-8f;
}

__device__ float g_C[BSN], g_Km[BSN], g_gK[BSN];
__device__ __align__(16) float g_k[BN * D];
__device__ __align__(16) float g_v[BN * D];
__device__ float g_knorm[BN], g_logit[BN], g_atil[BN], g_inva[BN];
__device__ float g_u[8 * BN];
__device__ float g_pv2[2 * PV2], g_pdv2[2 * PV2], g_pgn2[NBLK];
__device__ unsigned g_barcnt[B];
__device__ float g_amax[B], g_asum[B];
__device__ float g_slots[BSl * D], g_q[BSl * D], g_qn[BSl], g_btil[BSl], g_invb[BSl];
__device__ float g_upd[BSl * D], g_updp[B * 16 * S * D], g_posp[B * 16 * S * 2];

// ---- helpers ----
DI float blk_sum64(float v, float* sred, int tid) {
    sred[tid] = v; __syncthreads();
#pragma unroll
    for (int o = 32; o; o >>= 1) { if (tid < o) sred[tid] += sred[tid + o]; __syncthreads(); }
    float r = sred[0]; __syncthreads();
    return r;
}
DI float dot64(const float4* __restrict__ w, const float* __restrict__ x) {
    float a0 = 0.f, a1 = 0.f, a2 = 0.f, a3 = 0.f;
#pragma unroll
    for (int i = 0; i < 16; i++) {
        float4 t = w[i];
        a0 += x[4 * i] * t.x; a1 += x[4 * i + 1] * t.y;
        a2 += x[4 * i + 2] * t.z; a3 += x[4 * i + 3] * t.w;
    }
    return (a0 + a1) + (a2 + a3);
}

// per-batch grid barrier: monotonic counter, reset by k_slotprep each launch
DI void gbar(int b, unsigned goal) {
    __syncthreads();
    if (threadIdx.x == 0) {
        __threadfence();
        atomicAdd(&g_barcnt[b], 1u);
        volatile unsigned* p = &g_barcnt[b];
        while (*p < goal) __nanosleep(32);
        __threadfence();
    }
    __syncthreads();
}

// block-reduce 7 accumulators (8 warps) -> per-(b,s,chunk) partials, fixed order
DI void red7(const float* acc, float* outbase, int b, int c) {
    int tid = threadIdx.x, lane = tid & 31, w = tid >> 5;
    __shared__ float sm7[7][8];
#pragma unroll
    for (int s = 0; s < 7; s++) {
        float v = acc[s];
#pragma unroll
        for (int o = 16; o; o >>= 1) v += __shfl_down_sync(0xffffffffu, v, o);
        if (lane == 0) sm7[s][w] = v;
    }
    __syncthreads();
    if (tid < 7) {
        float t = 0.f;
#pragma unroll
        for (int ww = 0; ww < 8; ww++) t += sm7[tid][ww];
        outbase[(b * 7 + tid) * NCH + c] = t;
    }
    __syncthreads();
}
DI void red1(float v, float* out) {
    int tid = threadIdx.x, lane = tid & 31, w = tid >> 5;
    __shared__ float s8[8];
#pragma unroll
    for (int o = 16; o; o >>= 1) v += __shfl_down_sync(0xffffffffu, v, o);
    if (lane == 0) s8[w] = v;
    __syncthreads();
    if (tid == 0) {
        float t = 0.f;
#pragma unroll
        for (int ww = 0; ww < 8; ww++) t += s8[ww];
        *out = t;
    }
    __syncthreads();
}
// reduce chunk partials -> v = btil / sum; optionally store into smem v-history
DI void vred(const float* pbase, int b, int storeidx, float* svh, float* sv, const float* sbt) {
    int tid = threadIdx.x;
    if (tid < 7) {
        float sum = 0.f;
#pragma unroll
        for (int c2 = 0; c2 < NCH; c2++) sum += __ldcg(&pbase[(b * 7 + tid) * NCH + c2]);
        float vv = __fdividef(sbt[tid], sum);
        sv[tid] = vv;
        if (storeidx >= 0) svh[storeidx * 7 + tid] = vv;
    }
    __syncthreads();
}

// ---- kernels ----
__global__ void k_init(const float* __restrict__ mu, const float* __restrict__ sg,
                       const float* __restrict__ noise) {
    int i = blockIdx.x * 256 + threadIdx.x;
    if (i < BSl * D) {
        int d = i & 63;
        g_slots[i] = mu[d] + (fabsf(sg[d]) + EPS) * noise[i];
    }
}

__global__ __launch_bounds__(128) void k_lnkv(
    const float* __restrict__ inp, const float* __restrict__ Wk, const float* __restrict__ Wv,
    const float* __restrict__ lng, const float* __restrict__ lnb,
    const float* __restrict__ wiw, const float* __restrict__ wib) {
    __shared__ float4 sWk[1024], sWv[1024];
    __shared__ float swi[64], sg[64], sb[64];
    int tid = threadIdx.x;
    const float4* wk4 = (const float4*)Wk; const float4* wv4 = (const float4*)Wv;
    for (int i = tid; i < 1024; i += 128) { sWk[i] = wk4[i]; sWv[i] = wv4[i]; }
    if (tid < 64) { swi[tid] = wiw[tid]; sg[tid] = lng[tid]; sb[tid] = lnb[tid]; }
    __syncthreads();
    int token = blockIdx.x * 128 + tid;
    float x[64];
    const float4* ip = (const float4*)(inp + (size_t)token * 64);
#pragma unroll
    for (int i = 0; i < 16; i++) {
        float4 t = ip[i];
        x[4 * i] = t.x; x[4 * i + 1] = t.y; x[4 * i + 2] = t.z; x[4 * i + 3] = t.w;
    }
    float m = 0.f;
#pragma unroll
    for (int i = 0; i < 64; i++) m += x[i];
    m *= (1.f / 64);
    float var = 0.f;
#pragma unroll
    for (int i = 0; i < 64; i++) { float dd = x[i] - m; var += dd * dd; }
    float inv = rsqrtf(var * (1.f / 64) + LN_EPS);
    float lg = 0.f;
#pragma unroll
    for (int i = 0; i < 64; i++) { x[i] = (x[i] - m) * inv * sg[i] + sb[i]; lg += x[i] * swi[i]; }
    g_logit[token] = lg + wib[0];
    float kn = 0.f;
    float4* kp = (float4*)(g_k + (size_t)token * 64);
#pragma unroll 2
    for (int j = 0; j < 64; j += 4) {
        float4 o;
        o.x = dot64(sWk + (j + 0) * 16, x); o.y = dot64(sWk + (j + 1) * 16, x);
        o.z = dot64(sWk + (j + 2) * 16, x); o.w = dot64(sWk + (j + 3) * 16, x);
        kn += o.x * o.x + o.y * o.y + o.z * o.z + o.w * o.w;
        kp[j >> 2] = o;
    }
    g_knorm[token] = kn;
    float4* vp = (float4*)(g_v + (size_t)token * 64);
#pragma unroll 2
    for (int j = 0; j < 64; j += 4) {
        float4 o;
        o.x = dot64(sWv + (j + 0) * 16, x); o.y = dot64(sWv + (j + 1) * 16, x);
        o.z = dot64(sWv + (j + 2) * 16, x); o.w = dot64(sWv + (j + 3) * 16, x);
        vp[j >> 2] = o;
    }
}

__global__ __launch_bounds__(1024) void k_areduce() {
    int b = blockIdx.x, tid = threadIdx.x;
    __shared__ float sm[1024];
    float m = -3.4e38f;
    for (int n = tid; n < N; n += 1024) m = fmaxf(m, g_logit[b * N + n]);
    sm[tid] = m; __syncthreads();
    for (int o = 512; o; o >>= 1) { if (tid < o) sm[tid] = fmaxf(sm[tid], sm[tid + o]); __syncthreads(); }
    float mm = sm[0]; __syncthreads();
    float s = 0.f;
    for (int n = tid; n < N; n += 1024) s += __expf(g_logit[b * N + n] - mm);
    sm[tid] = s; __syncthreads();
    for (int o = 512; o; o >>= 1) { if (tid < o) sm[tid] += sm[tid + o]; __syncthreads(); }
    if (tid == 0) { g_amax[b] = mm; g_asum[b] = sm[0]; }
}

__global__ void k_afin() {
    int i = blockIdx.x * 256 + threadIdx.x;
    int b = i >> 14;
    float at = __expf(g_logit[i] - g_amax[b]) * (7.f / g_asum[b]) + EPS;
    g_atil[i] = at; g_inva[i] = 1.f / at;
}

__global__ __launch_bounds__(64) void k_slotprep(
    const float* __restrict__ lng, const float* __restrict__ lnb,
    const float* __restrict__ Wq, const float* __restrict__ wsw, const float* __restrict__ wsb) {
    int b = blockIdx.x, tid = threadIdx.x;
    if (tid == 0) g_barcnt[b] = 0;   // reset per-batch barrier for the following k_mesh
    __shared__ float xln[7][64], sred[64], sl[7];
    float wsv = wsw[tid];
    for (int s = 0; s < 7; s++) {
        float v = g_slots[(b * 7 + s) * 64 + tid];
        float m = blk_sum64(v, sred, tid) * (1.f / 64);
        float dd = v - m;
        float var = blk_sum64(dd * dd, sred, tid) * (1.f / 64);
        float x = dd * rsqrtf(var + LN_EPS) * lng[tid] + lnb[tid];
        xln[s][tid] = x;
        float lg = blk_sum64(x * wsv, sred, tid);
        if (tid == 0) sl[s] = lg + wsb[0];
    }
    __syncthreads();
    if (tid == 0) {
        float mx = sl[0];
#pragma unroll
        for (int s = 1; s < 7; s++) mx = fmaxf(mx, sl[s]);
        float e[7], ss = 0.f;
#pragma unroll
        for (int s = 0; s < 7; s++) { e[s] = __expf(sl[s] - mx); ss += e[s]; }
#pragma unroll
        for (int s = 0; s < 7; s++) {
            float bt = e[s] / ss * 7.f + EPS;
            g_btil[b * 7 + s] = bt; g_invb[b * 7 + s] = 1.f / bt;
        }
    }
    __syncthreads();
    for (int s = 0; s < 7; s++) {
        float acc = 0.f;
        const float* wr = Wq + tid * 64;
#pragma unroll 8
        for (int j = 0; j < 64; j++) acc += xln[s][j] * wr[j];
        g_q[(b * 7 + s) * 64 + tid] = acc;
        float qn = blk_sum64(acc * acc, sred, tid);
        if (tid == 0) g_qn[b * 7 + s] = qn;
    }
}

__global__ __launch_bounds__(256) void k_buildC() {
    int b = blockIdx.x >> 6, chunk = blockIdx.x & 63, tid = threadIdx.x;
    __shared__ float sq[7][64], sqn[7];
    for (int i = tid; i < 448; i += 256) sq[i >> 6][i & 63] = g_q[b * 448 + i];
    if (tid < 7) sqn[tid] = g_qn[b * 7 + tid];
    __syncthreads();
    int n = chunk * 256 + tid;
    float kx[64];
    const float4* kp = (const float4*)(g_k + (size_t)(b * N + n) * 64);
#pragma unroll
    for (int i = 0; i < 16; i++) {
        float4 t = kp[i];
        kx[4 * i] = t.x; kx[4 * i + 1] = t.y; kx[4 * i + 2] = t.z; kx[4 * i + 3] = t.w;
    }
    float kn = g_knorm[b * N + n];
    int base = b * 7 * N + n;
#pragma unroll
    for (int s = 0; s < 7; s++) {
        float d0 = 0.f, d1 = 0.f;
#pragma unroll
        for (int j = 0; j < 64; j += 2) { d0 += kx[j] * sq[s][j]; d1 += kx[j + 1] * sq[s][j + 1]; }
        float sqd = kn + sqn[s] - 2.f * (d0 + d1);
        float c = sqrtf(fmaxf(sqd, 1e-12f));
        g_C[base + s * N] = c;
        g_Km[base + s * N] = __expf(-c);
    }
}

// ===== fused mesh + sinkhorn + Pout: one launch per slot-attention iteration =====
__global__ __launch_bounds__(256, 4) void k_mesh(float* __restrict__ outa) {
    int b = blockIdx.x >> 4, c = blockIdx.x & 15, tid = threadIdx.x;
    int gb = b * N;
    int cb = b * 7 * N;
    int tok0 = c * TOKB;
    __shared__ float sv[7], svh[9 * 7], sbt[7], sib[7], ssd[7], ssv[7], sgn[1];
    if (tid < 7) {
        sbt[tid] = g_btil[b * 7 + tid];
        sib[tid] = g_invb[b * 7 + tid];
        svh[tid] = 1.f;                     // v_0 = 1
    }
    __syncthreads();
    unsigned nbar = 0;
    float rowm[4];                           // rowM in mesh-bwd; re-used as u_16 in final phase

    for (int e = 0; e < 5; e++) {            // e=0..3 mesh grad evals, e=4 final 16-iter sinkhorn
        const bool mesh = (e < 4);
        const int tmax = mesh ? 8 : 16;
        // ---- forward iterations ----
        for (int t = 1; t <= tmax; t++) {
            if (t == 1) {
                if (tid < 7) sv[tid] = 1.f;
                __syncthreads();
            } else {
                vred(g_pv2 + ((t - 2) & 1) * PV2, b, mesh ? (t - 1) : -1, svh, sv, sbt);
            }
            float svr[7];
#pragma unroll
            for (int s = 0; s < 7; s++) svr[s] = sv[s];
            float ign = (t == 1 && e > 0) ? __fdividef(1.f, sgn[0]) : 0.f;
            float acc[7] = {0.f, 0.f, 0.f, 0.f, 0.f, 0.f, 0.f};
#pragma unroll
            for (int j = 0; j < 4; j++) {
                int n = tok0 + j * 256 + tid;
                int idx = cb + n;
                float km[7];
                if (t == 1 && e > 0) {       // apply normalized gradient step, rebuild Km
#pragma unroll
                    for (int s = 0; s < 7; s++) {
                        float c0 = g_C[idx + s * N] - g_gK[idx + s * N] * ign;
                        g_C[idx + s * N] = c0;
                        km[s] = __expf(-c0);
                        g_Km[idx + s * N] = km[s];
                    }
                } else {
#pragma unroll
                    for (int s = 0; s < 7; s++) km[s] = g_Km[idx + s * N];
                }
                float den = 0.f;
#pragma unroll
                for (int s = 0; s < 7; s++) den += km[s] * svr[s];
                float u = __fdividef(g_atil[gb + n], den);
                if (mesh) g_u[(t - 1) * BN + gb + n] = u;
                else if (t == tmax) rowm[j] = u;          // keep u_16 in regs
#pragma unroll
                for (int s = 0; s < 7; s++) acc[s] += km[s] * u;
            }
            red7(acc, g_pv2 + ((t - 1) & 1) * PV2, b, c);
            gbar(b, ++nbar * NCH);
        }
        if (!mesh) break;
        // ---- backward init (t=8): M = gP*P, gK = -M, rowM, colsum partials ----
        vred(g_pv2 + PV2, b, 8, svh, sv, sbt);
        {
            float svr[7];
#pragma unroll
            for (int s = 0; s < 7; s++) svr[s] = sv[s];
            float acc[7] = {0.f, 0.f, 0.f, 0.f, 0.f, 0.f, 0.f};
#pragma unroll
            for (int j = 0; j < 4; j++) {
                int n = tok0 + j * 256 + tid;
                int idx = cb + n;
                float u8 = g_u[7 * BN + gb + n];
                float rm = 0.f;
#pragma unroll
                for (int s = 0; s < 7; s++) {
                    float km = g_Km[idx + s * N];
                    float P = km * u8 * svr[s];
                    float gp = -(__logf(P + EPS) + __fdividef(P, P + EPS));
                    float mm = gp * P;
                    g_gK[idx + s * N] = -mm;
                    rm += mm; acc[s] += mm;
                }
                rowm[j] = rm;
            }
            red7(acc, g_pdv2, b, c);
            gbar(b, ++nbar * NCH);
        }
        // ---- backward adjoint chain t=8..1 ----
        for (int t = 8; t >= 1; t--) {
            int qin = (8 - t) & 1;
            if (tid < 7) {
                float dv = 0.f;
#pragma unroll
                for (int c2 = 0; c2 < NCH; c2++)
                    dv += __ldcg(&g_pdv2[qin * PV2 + (b * 7 + tid) * NCH + c2]);
                float vt = svh[t * 7 + tid];
                float fac = (t == 8) ? vt : vt * vt;
                ssd[tid] = -dv * fac * sib[tid];
                ssv[tid] = svh[(t - 1) * 7 + tid];
            }
            __syncthreads();
            float sdr[7], svm[7];
#pragma unroll
            for (int s = 0; s < 7; s++) { sdr[s] = ssd[s]; svm[s] = ssv[s]; }
            float acc[7] = {0.f, 0.f, 0.f, 0.f, 0.f, 0.f, 0.f};
            float gsq = 0.f;
#pragma unroll
            for (int j = 0; j < 4; j++) {
                int n = tok0 + j * 256 + tid;
                int idx = cb + n;
                float ut = g_u[(t - 1) * BN + gb + n];
                float km[7];
#pragma unroll
                for (int s = 0; s < 7; s++) km[s] = g_Km[idx + s * N];
                float du = 0.f;
#pragma unroll
                for (int s = 0; s < 7; s++) du += sdr[s] * km[s];
                if (t == 8) du += __fdividef(rowm[j], ut);
                float dE = -du * ut * ut * g_inva[gb + n];
                if (t > 1) {
#pragma unroll
                    for (int s = 0; s < 7; s++) {
                        g_gK[idx + s * N] -= km[s] * (sdr[s] * ut + dE * svm[s]);
                        acc[s] += dE * km[s];
                    }
                } else {
#pragma unroll
                    for (int s = 0; s < 7; s++) {
                        float g = g_gK[idx + s * N] - km[s] * (sdr[s] * ut + dE * svm[s]);
                        g_gK[idx + s * N] = g;
                        gsq += g * g;
                    }
                }
            }
            if (t > 1) red7(acc, g_pdv2 + ((9 - t) & 1) * PV2, b, c);
            else red1(gsq, &g_pgn2[b * NCH + c]);
            gbar(b, ++nbar * NCH);
        }
        // ---- grad norm for this batch ----
        if (tid == 0) {
            float sum = 0.f;
#pragma unroll
            for (int c2 = 0; c2 < NCH; c2++) sum += __ldcg(&g_pgn2[b * NCH + c2]);
            sgn[0] = sqrtf(sum) + EPS;
        }
        __syncthreads();
    }
    // ---- P output: v_16 from final partials (parity 1), u_16 in rowm ----
    vred(g_pv2 + PV2, b, -1, svh, sv, sbt);
    float svr[7];
#pragma unroll
    for (int s = 0; s < 7; s++) svr[s] = sv[s];
#pragma unroll
    for (int j = 0; j < 4; j++) {
        int n = tok0 + j * 256 + tid;
        int idx = cb + n;
        float u = rowm[j];
#pragma unroll
        for (int s = 0; s < 7; s++) outa[idx + s * N] = g_Km[idx + s * N] * u * svr[s];
    }
}

// updates + slot_pos: V read ONCE per launch (dims across lanes, tokens across warps)
__global__ __launch_bounds__(256) void k_upd(const float* __restrict__ outa) {
    int b = blockIdx.x >> 4, chunk = blockIdx.x & 15;
    int tid = threadIdx.x, w = tid >> 5, d2 = tid & 31;
    int t0 = chunk * 1024 + w * 128;
    const float2* v2 = (const float2*)g_v + ((size_t)(b * N) + t0) * 32 + d2;
    const float* Pb = outa + (size_t)b * 7 * N;
    float accx[7] = {0,0,0,0,0,0,0}, accy[7] = {0,0,0,0,0,0,0};
    float posx[7] = {0,0,0,0,0,0,0}, posy[7] = {0,0,0,0,0,0,0};
    for (int i = 0; i < 128; i++) {
        int n = t0 + i;
        float2 vv = v2[(size_t)i * 32];
        float p[7];
#pragma unroll
        for (int s = 0; s < 7; s++) p[s] = Pb[s * N + n];   // lane-broadcast
#pragma unroll
        for (int s = 0; s < 7; s++) { accx[s] += p[s] * vv.x; accy[s] += p[s] * vv.y; }
        if (d2 == 0) {
            float gx = (n & 127) * (1.f / 127.f), gy = (n >> 7) * (1.f / 127.f);
#pragma unroll
            for (int s = 0; s < 7; s++) { posx[s] += p[s] * gx; posy[s] += p[s] * gy; }
        }
    }
    __shared__ float sacc[8][7][64];
    __shared__ float spos[8][7][2];
#pragma unroll
    for (int s = 0; s < 7; s++) {
        sacc[w][s][2 * d2] = accx[s];
        sacc[w][s][2 * d2 + 1] = accy[s];
    }
    if (d2 == 0) {
#pragma unroll
        for (int s = 0; s < 7; s++) { spos[w][s][0] = posx[s]; spos[w][s][1] = posy[s]; }
    }
    __syncthreads();
    for (int idx = tid; idx < 448; idx += 256) {
        int s = idx >> 6, d = idx & 63;
        float t = 0.f;
#pragma unroll
        for (int w2 = 0; w2 < 8; w2++) t += sacc[w2][s][d];
        g_updp[((b * 16 + chunk) * 7 + s) * 64 + d] = t;
    }
    if (tid < 14) {
        int s = tid >> 1, k2 = tid & 1;
        float t = 0.f;
#pragma unroll
        for (int w2 = 0; w2 < 8; w2++) t += spos[w2][s][k2];
        g_posp[((b * 16 + chunk) * 7 + s) * 2 + k2] = t;
    }
}

__global__ __launch_bounds__(64) void k_updfin(float* __restrict__ outp) {
    int bs = blockIdx.x, tid = threadIdx.x;
    int b = bs / 7, s = bs % 7;
    float acc = 0.f;
#pragma unroll
    for (int c = 0; c < 16; c++) acc += g_updp[((b * 16 + c) * 7 + s) * 64 + tid];
    g_upd[bs * 64 + tid] = acc;
    if (tid < 2) {
        float p = 0.f;
#pragma unroll
        for (int c = 0; c < 16; c++) p += g_posp[((b * 16 + c) * 7 + s) * 2 + tid];
        outp[bs * 2 + tid] = p;
    }
}

__global__ __launch_bounds__(64) void k_gruff(
    const float* __restrict__ Wih, const float* __restrict__ Whh,
    const float* __restrict__ bih, const float* __restrict__ bhh,
    const float* __restrict__ f1w, const float* __restrict__ f1b,
    const float* __restrict__ f2w, const float* __restrict__ f2b,
    const float* __restrict__ lng, const float* __restrict__ lnb,
    float* __restrict__ outs, int last) {
    int bs = blockIdx.x, tid = threadIdx.x;
    __shared__ float su[64], sp[64], sx[64], shid[128], sred[64];
    su[tid] = g_upd[bs * 64 + tid];
    sp[tid] = g_slots[bs * 64 + tid];
    __syncthreads();
    float ir = bih[tid], iz = bih[64 + tid], inn = bih[128 + tid];
    float hr = bhh[tid], hz = bhh[64 + tid], hn = bhh[128 + tid];
#pragma unroll 4
    for (int d = 0; d < 64; d++) {
        float uu = su[d], pp = sp[d];
        ir += Wih[tid * 64 + d] * uu;
        iz += Wih[(64 + tid) * 64 + d] * uu;
        inn += Wih[(128 + tid) * 64 + d] * uu;
        hr += Whh[tid * 64 + d] * pp;
        hz += Whh[(64 + tid) * 64 + d] * pp;
        hn += Whh[(128 + tid) * 64 + d] * pp;
    }
    float r = 1.f / (1.f + expf(-(ir + hr)));
    float z = 1.f / (1.f + expf(-(iz + hz)));
    float nn = tanhf(inn + r * hn);
    float h = (1.f - z) * nn + z * sp[tid];
    float m = blk_sum64(h, sred, tid) * (1.f / 64);
    float dd = h - m;
    float var = blk_sum64(dd * dd, sred, tid) * (1.f / 64);
    sx[tid] = dd * rsqrtf(var + LN_EPS) * lng[tid] + lnb[tid];
    __syncthreads();
#pragma unroll
    for (int jj = 0; jj < 2; jj++) {
        int j = tid + jj * 64;
        float a = f1b[j];
#pragma unroll 4
        for (int d = 0; d < 64; d++) a += sx[d] * f1w[j * 64 + d];
        shid[j] = fmaxf(a, 0.f);
    }
    __syncthreads();
    float o = f2b[tid];
#pragma unroll 4
    for (int j = 0; j < 128; j++) o += shid[j] * f2w[tid * 128 + j];
    float ns = h + o;
    g_slots[bs * 64 + tid] = ns;
    if (last) outs[bs * 64 + tid] = ns;
}

// ---- host ----
extern "C" void kernel_launch(void* const* d_in, const int* in_sizes, int n_in,
                              void* d_out, int out_size) {
    const float* inp  = (const float*)d_in[0];
    const float* noi  = (const float*)d_in[1];
    const float* mu   = (const float*)d_in[2];
    const float* sig  = (const float*)d_in[3];
    const float* Wq   = (const float*)d_in[4];
    const float* Wk   = (const float*)d_in[5];
    const float* Wv   = (const float*)d_in[6];
    const float* Wih  = (const float*)d_in[7];
    const float* Whh  = (const float*)d_in[8];
    const float* bih  = (const float*)d_in[9];
    const float* bhh  = (const float*)d_in[10];
    const float* f1w  = (const float*)d_in[11];
    const float* f1b  = (const float*)d_in[12];
    const float* f2w  = (const float*)d_in[13];
    const float* f2b  = (const float*)d_in[14];
    const float* ling = (const float*)d_in[15];
    const float* linb = (const float*)d_in[16];
    const float* lsg  = (const float*)d_in[17];
    const float* lsb  = (const float*)d_in[18];
    const float* lfg  = (const float*)d_in[19];
    const float* lfb  = (const float*)d_in[20];
    const float* wiw  = (const float*)d_in[21];
    const float* wib  = (const float*)d_in[22];
    const float* wsw  = (const float*)d_in[23];
    const float* wsb  = (const float*)d_in[24];
    float* out = (float*)d_out;
    float* out_slots = out;
    float* out_pos   = out + BSl * D;
    float* out_attn  = out + BSl * D + BSl * 2;

    k_init<<<56, 256>>>(mu, sig, noi);
    k_lnkv<<<BN / 128, 128>>>(inp, Wk, Wv, ling, linb, wiw, wib);
    k_areduce<<<B, 1024>>>();
    k_afin<<<BN / 256, 256>>>();

    for (int it = 0; it < 3; it++) {
        k_slotprep<<<B, 64>>>(lsg, lsb, Wq, wsw, wsb);
        k_buildC<<<B * 64, 256>>>();
        k_mesh<<<NBLK, 256>>>(out_attn);
        k_upd<<<B * 16, 256>>>(out_attn);
        k_updfin<<<BSl, 64>>>(out_pos);
        k_gruff<<<BSl, 64>>>(Wih, Whh, bih, bhh, f1w, f1b, f2w, f2b, lfg, lfb,
                             out_slots, it == 2 ? 1 : 0);
    }
}